// round 1
// baseline (speedup 1.0000x reference)
#include <cuda_runtime.h>
#include <math.h>

// Problem constants (fixed by the reference)
#define Bsz 4
#define Tsz 2048
#define Dsz 1024

// GEMM tiling
#define BM 128
#define BN 128
#define BK 16
#define NT 256   // threads per block

// Scratch (allocation-free rule: __device__ globals)
__device__ float g_q[(size_t)Bsz * Tsz * Dsz];
__device__ float g_k[(size_t)Bsz * Tsz * Dsz];
__device__ float g_v[(size_t)Bsz * Tsz * Dsz];
__device__ float g_s[(size_t)Bsz * Tsz * Tsz];

// ---------------------------------------------------------------------------
// C[M,N] = A[M,K] @ B[N,K]^T   (both row-major, K-major inner dim)
// Used for: QKV projections (x @ W^T) and S = Q @ K^T.
// causal=1: skip tiles entirely above the diagonal (S is never read there).
// ---------------------------------------------------------------------------
__global__ __launch_bounds__(NT) void gemm_nt_kernel(
    const float* __restrict__ A, const float* __restrict__ B,
    float* __restrict__ C, int N, int K, int causal,
    int bsA, int bsB, int bsC)
{
    int b = blockIdx.z;
    A += (size_t)b * bsA;
    B += (size_t)b * bsB;
    C += (size_t)b * bsC;

    const int row0 = blockIdx.y * BM;
    const int col0 = blockIdx.x * BN;
    if (causal && col0 >= row0 + BM) return;  // tile fully above diagonal

    __shared__ float As[BK][BM];
    __shared__ float Bs[BK][BN];

    const int tid = threadIdx.x;
    const int lr = tid >> 2;          // 0..63  (tile row for loads)
    const int lc = (tid & 3) << 2;    // 0,4,8,12 (k offset for loads)
    const int tx = tid & 15;          // 0..15 (output col group)
    const int ty = tid >> 4;          // 0..15 (output row group)

    float acc[8][8];
#pragma unroll
    for (int i = 0; i < 8; i++)
#pragma unroll
        for (int j = 0; j < 8; j++) acc[i][j] = 0.f;

    for (int k0 = 0; k0 < K; k0 += BK) {
#pragma unroll
        for (int r = 0; r < 2; r++) {
            const int rr = lr + r * 64;
            float4 va = *(const float4*)(&A[(size_t)(row0 + rr) * K + k0 + lc]);
            As[lc + 0][rr] = va.x; As[lc + 1][rr] = va.y;
            As[lc + 2][rr] = va.z; As[lc + 3][rr] = va.w;
            float4 vb = *(const float4*)(&B[(size_t)(col0 + rr) * K + k0 + lc]);
            Bs[lc + 0][rr] = vb.x; Bs[lc + 1][rr] = vb.y;
            Bs[lc + 2][rr] = vb.z; Bs[lc + 3][rr] = vb.w;
        }
        __syncthreads();

#pragma unroll
        for (int kk = 0; kk < BK; kk++) {
            float ra[8], rb[8];
#pragma unroll
            for (int i = 0; i < 8; i++) ra[i] = As[kk][ty * 8 + i];
#pragma unroll
            for (int j = 0; j < 8; j++) rb[j] = Bs[kk][tx * 8 + j];
#pragma unroll
            for (int i = 0; i < 8; i++)
#pragma unroll
                for (int j = 0; j < 8; j++)
                    acc[i][j] = fmaf(ra[i], rb[j], acc[i][j]);
        }
        __syncthreads();
    }

#pragma unroll
    for (int i = 0; i < 8; i++) {
        const int r = row0 + ty * 8 + i;
#pragma unroll
        for (int j = 0; j < 8; j += 4) {
            float4 v4 = make_float4(acc[i][j], acc[i][j + 1],
                                    acc[i][j + 2], acc[i][j + 3]);
            *(float4*)(&C[(size_t)r * N + col0 + tx * 8 + j]) = v4;
        }
    }
}

// ---------------------------------------------------------------------------
// C[M,N] = A[M,K] @ B[K,N]   (row-major).  Used for O = P @ V.
// klimit=1: K loop clipped to row0+BM (causal P has zeros beyond that,
// guaranteed by the softmax kernel's tail zero-fill).
// ---------------------------------------------------------------------------
__global__ __launch_bounds__(NT) void gemm_nn_kernel(
    const float* __restrict__ A, const float* __restrict__ B,
    float* __restrict__ C, int N, int K, int klimit,
    int bsA, int bsB, int bsC)
{
    int b = blockIdx.z;
    A += (size_t)b * bsA;
    B += (size_t)b * bsB;
    C += (size_t)b * bsC;

    const int row0 = blockIdx.y * BM;
    const int col0 = blockIdx.x * BN;
    const int kend = klimit ? min(K, row0 + BM) : K;

    __shared__ float As[BK][BM];
    __shared__ float Bs[BK][BN];

    const int tid = threadIdx.x;
    const int lr = tid >> 2;          // A tile row
    const int lc = (tid & 3) << 2;    // A tile k offset
    const int br = tid >> 5;          // B tile row (0..7, x2)
    const int bc = (tid & 31) << 2;   // B tile col (float4)
    const int tx = tid & 15;
    const int ty = tid >> 4;

    float acc[8][8];
#pragma unroll
    for (int i = 0; i < 8; i++)
#pragma unroll
        for (int j = 0; j < 8; j++) acc[i][j] = 0.f;

    for (int k0 = 0; k0 < kend; k0 += BK) {
#pragma unroll
        for (int r = 0; r < 2; r++) {
            const int rr = lr + r * 64;
            float4 va = *(const float4*)(&A[(size_t)(row0 + rr) * K + k0 + lc]);
            As[lc + 0][rr] = va.x; As[lc + 1][rr] = va.y;
            As[lc + 2][rr] = va.z; As[lc + 3][rr] = va.w;
        }
#pragma unroll
        for (int r = 0; r < 2; r++) {
            const int rb_ = br + r * 8;
            float4 vb = *(const float4*)(&B[(size_t)(k0 + rb_) * N + col0 + bc]);
            *(float4*)(&Bs[rb_][bc]) = vb;
        }
        __syncthreads();

#pragma unroll
        for (int kk = 0; kk < BK; kk++) {
            float ra[8], rb[8];
#pragma unroll
            for (int i = 0; i < 8; i++) ra[i] = As[kk][ty * 8 + i];
#pragma unroll
            for (int j = 0; j < 8; j++) rb[j] = Bs[kk][tx * 8 + j];
#pragma unroll
            for (int i = 0; i < 8; i++)
#pragma unroll
                for (int j = 0; j < 8; j++)
                    acc[i][j] = fmaf(ra[i], rb[j], acc[i][j]);
        }
        __syncthreads();
    }

#pragma unroll
    for (int i = 0; i < 8; i++) {
        const int r = row0 + ty * 8 + i;
#pragma unroll
        for (int j = 0; j < 8; j += 4) {
            float4 v4 = make_float4(acc[i][j], acc[i][j + 1],
                                    acc[i][j + 2], acc[i][j + 3]);
            *(float4*)(&C[(size_t)r * N + col0 + tx * 8 + j]) = v4;
        }
    }
}

// ---------------------------------------------------------------------------
// Causal row softmax over S (in place): row r uses entries [0, r], applies
// scale 1/sqrt(1024)=1/32, and zero-fills (r, tile_end) so the PV GEMM can
// run unmasked with its K loop clipped to the 128-tile boundary.
// ---------------------------------------------------------------------------
__device__ __forceinline__ float warp_max_f(float v) {
#pragma unroll
    for (int o = 16; o; o >>= 1) v = fmaxf(v, __shfl_xor_sync(0xffffffffu, v, o));
    return v;
}
__device__ __forceinline__ float warp_sum_f(float v) {
#pragma unroll
    for (int o = 16; o; o >>= 1) v += __shfl_xor_sync(0xffffffffu, v, o);
    return v;
}
__device__ float block_reduce_max(float v) {
    __shared__ float sm[NT / 32];
    v = warp_max_f(v);
    if ((threadIdx.x & 31) == 0) sm[threadIdx.x >> 5] = v;
    __syncthreads();
    float r = sm[0];
#pragma unroll
    for (int i = 1; i < NT / 32; i++) r = fmaxf(r, sm[i]);
    __syncthreads();
    return r;
}
__device__ float block_reduce_sum(float v) {
    __shared__ float sm2[NT / 32];
    v = warp_sum_f(v);
    if ((threadIdx.x & 31) == 0) sm2[threadIdx.x >> 5] = v;
    __syncthreads();
    float r = 0.f;
#pragma unroll
    for (int i = 0; i < NT / 32; i++) r += sm2[i];
    __syncthreads();
    return r;
}

__global__ __launch_bounds__(NT) void softmax_causal_kernel(float* __restrict__ S)
{
    const int b = blockIdx.y;
    const int r = blockIdx.x;
    float* row = S + ((size_t)b * Tsz + r) * Tsz;
    const int len = r + 1;
    const int blk_end = ((r >> 7) + 1) << 7;  // next multiple of 128
    const float scale = 0.03125f;             // 1/sqrt(1024)

    float m = -INFINITY;
    for (int i = threadIdx.x; i < len; i += NT) m = fmaxf(m, row[i]);
    m = block_reduce_max(m);

    float s = 0.f;
    for (int i = threadIdx.x; i < len; i += NT) {
        float e = __expf((row[i] - m) * scale);
        row[i] = e;
        s += e;
    }
    s = block_reduce_sum(s);
    const float inv = 1.f / s;

    for (int i = threadIdx.x; i < len; i += NT) row[i] *= inv;
    for (int i = len + threadIdx.x; i < blk_end; i += NT) row[i] = 0.f;
}

// ---------------------------------------------------------------------------
// Launch
// ---------------------------------------------------------------------------
extern "C" void kernel_launch(void* const* d_in, const int* in_sizes, int n_in,
                              void* d_out, int out_size)
{
    (void)in_sizes; (void)n_in; (void)out_size;
    const float* x  = (const float*)d_in[0];
    const float* Wq = (const float*)d_in[1];
    const float* Wk = (const float*)d_in[2];
    const float* Wv = (const float*)d_in[3];
    float* out = (float*)d_out;

    float *q, *k, *v, *s;
    cudaGetSymbolAddress((void**)&q, g_q);
    cudaGetSymbolAddress((void**)&k, g_k);
    cudaGetSymbolAddress((void**)&v, g_v);
    cudaGetSymbolAddress((void**)&s, g_s);

    dim3 blk(NT);

    // QKV projections: [B*T, D] = x[B*T, D] @ W[D, D]^T
    dim3 gq(Dsz / BN, (Bsz * Tsz) / BM, 1);
    gemm_nt_kernel<<<gq, blk>>>(x, Wq, q, Dsz, Dsz, 0, 0, 0, 0);
    gemm_nt_kernel<<<gq, blk>>>(x, Wk, k, Dsz, Dsz, 0, 0, 0, 0);
    gemm_nt_kernel<<<gq, blk>>>(x, Wv, v, Dsz, Dsz, 0, 0, 0, 0);

    // S_b = Q_b @ K_b^T (causal tile skipping; no masking needed — softmax
    // only ever reads k <= r)
    dim3 gs(Tsz / BN, Tsz / BM, Bsz);
    gemm_nt_kernel<<<gs, blk>>>(q, k, s, Tsz, Dsz, 1,
                                Tsz * Dsz, Tsz * Dsz, Tsz * Tsz);

    // Causal softmax (in place, with tail zero-fill to the 128 boundary)
    softmax_causal_kernel<<<dim3(Tsz, Bsz), blk>>>(s);

    // O_b = P_b @ V_b with K loop clipped at row0+128
    dim3 gp(Dsz / BN, Tsz / BM, Bsz);
    gemm_nn_kernel<<<gp, blk>>>(s, v, out, Dsz, Tsz, 1,
                                Tsz * Tsz, Tsz * Dsz, Tsz * Dsz);
}

// round 3
// speedup vs baseline: 3.7970x; 3.7970x over previous
#include <cuda_runtime.h>
#include <cuda_fp16.h>
#include <stdint.h>
#include <math.h>

#define Bsz 4
#define Tsz 2048
#define Dsz 1024
#define BT  (Bsz * Tsz)

typedef __half h16;

// ---------------- scratch (__device__ globals; allocation-free rule) -------
__device__ __align__(16) float g_q[(size_t)BT * Dsz];
__device__ __align__(16) float g_k[(size_t)BT * Dsz];
__device__ __align__(16) float g_v[(size_t)BT * Dsz];
__device__ __align__(16) float g_s[(size_t)Bsz * Tsz * Tsz];
__device__ __align__(16) h16 g_xf[(size_t)BT * Dsz];
__device__ __align__(16) h16 g_wh[3][(size_t)Dsz * Dsz];
__device__ __align__(16) h16 g_wl[3][(size_t)Dsz * Dsz];
__device__ __align__(16) h16 g_qf[(size_t)BT * Dsz];
__device__ __align__(16) h16 g_kh[(size_t)BT * Dsz];
__device__ __align__(16) h16 g_kl[(size_t)BT * Dsz];
__device__ __align__(16) h16 g_vth[(size_t)BT * Dsz];
__device__ __align__(16) h16 g_vtl[(size_t)BT * Dsz];
__device__ __align__(16) h16 g_pf[(size_t)Bsz * Tsz * Tsz];

// ---------------- low-level helpers (all plain sm_80-era PTX) ---------------
__device__ __forceinline__ uint32_t smem_u32(const void* p) {
    uint32_t a;
    asm("{ .reg .u64 t; cvta.to.shared.u64 t, %1; cvt.u32.u64 %0, t; }"
        : "=r"(a) : "l"(p));
    return a;
}

#define CP_ASYNC16(dst, src) \
    asm volatile("cp.async.cg.shared.global [%0], [%1], 16;" \
                 :: "r"(dst), "l"(src))
#define CP_COMMIT() asm volatile("cp.async.commit_group;")
#define CP_WAIT1()  asm volatile("cp.async.wait_group 1;")

__device__ __forceinline__ void ldsm4(uint32_t& r0, uint32_t& r1,
                                      uint32_t& r2, uint32_t& r3,
                                      uint32_t addr) {
    asm volatile("ldmatrix.sync.aligned.m8n8.x4.shared.b16 {%0,%1,%2,%3}, [%4];"
                 : "=r"(r0), "=r"(r1), "=r"(r2), "=r"(r3) : "r"(addr));
}

__device__ __forceinline__ void mma16816(float* d, const uint32_t* a,
                                         const uint32_t* b) {
    asm volatile(
        "mma.sync.aligned.m16n8k16.row.col.f32.f16.f16.f32 "
        "{%0,%1,%2,%3}, {%4,%5,%6,%7}, {%8,%9}, {%0,%1,%2,%3};"
        : "+f"(d[0]), "+f"(d[1]), "+f"(d[2]), "+f"(d[3])
        : "r"(a[0]), "r"(a[1]), "r"(a[2]), "r"(a[3]), "r"(b[0]), "r"(b[1]));
}

// ---------------- HMMA NT GEMM: C[M,N] = A[M,K] * B[N,K]^T ------------------
// A single fp16; B as fp16 hi/lo split (2 MMAs per product, fp32 accum).
// mode 0: full.  mode 1: causal tile skip.  mode 2: kend = row0+128.
#define KC    32
#define ROWB  80                 // 64B data + 16B pad per smem row
#define MATB  (128 * ROWB)       // 10240 B per matrix tile
#define STGB  (3 * MATB)         // A, Bh, Bl
#define SMEMB (2 * STGB)         // double buffered: 61440 B

__global__ void __launch_bounds__(256) hgemm_nt(
    const h16* __restrict__ Af, const h16* __restrict__ Bhp,
    const h16* __restrict__ Blp, float* __restrict__ C,
    int N, int K, int mode, long long sA, long long sB, long long sC)
{
    const int bz = blockIdx.z;
    Af  += (size_t)bz * sA;
    Bhp += (size_t)bz * sB;
    Blp += (size_t)bz * sB;
    C   += (size_t)bz * sC;

    const int row0 = blockIdx.y * 128;
    const int col0 = blockIdx.x * 128;
    if (mode == 1 && col0 >= row0 + 128) return;
    const int kend = (mode == 2) ? (row0 + 128) : K;
    const int nc = kend / KC;

    extern __shared__ char smc[];
    const uint32_t smb = smem_u32(smc);
    const int tid  = threadIdx.x;
    const int lane = tid & 31;
    const int wid  = tid >> 5;
    const int m0 = (wid & 1) * 64;     // warp tile 64x32, warps 2x4
    const int n0 = (wid >> 1) * 32;

    float acc[4][4][4];
#pragma unroll
    for (int i = 0; i < 4; i++)
#pragma unroll
        for (int j = 0; j < 4; j++)
#pragma unroll
            for (int q = 0; q < 4; q++) acc[i][j][q] = 0.f;

    const int lrow = tid >> 2;     // 0..63 (+64 second pass)
    const int lch  = tid & 3;      // 16B chunk within 64B row

    auto do_load = [&](int st, int k0) {
        const uint32_t sb = smb + (uint32_t)st * STGB;
        const h16* pA = Af  + (size_t)row0 * K + k0;
        const h16* pH = Bhp + (size_t)col0 * K + k0;
        const h16* pL = Blp + (size_t)col0 * K + k0;
#pragma unroll
        for (int j = 0; j < 2; j++) {
            const int row = lrow + j * 64;
            const size_t go = (size_t)row * K + lch * 8;
            const uint32_t so = sb + (uint32_t)(row * ROWB + lch * 16);
            CP_ASYNC16(so,            pA + go);
            CP_ASYNC16(so + MATB,     pH + go);
            CP_ASYNC16(so + 2 * MATB, pL + go);
        }
    };

    do_load(0, 0);
    CP_COMMIT();

    for (int c = 0; c < nc; c++) {
        if (c + 1 < nc) do_load((c + 1) & 1, (c + 1) * KC);
        CP_COMMIT();
        CP_WAIT1();
        __syncthreads();

        const uint32_t base = smb + (uint32_t)(c & 1) * STGB;
#pragma unroll
        for (int kk = 0; kk < 2; kk++) {          // two k16 steps per KC=32
            uint32_t a[4][4];
#pragma unroll
            for (int mi = 0; mi < 4; mi++) {
                const uint32_t ad = base +
                    (uint32_t)((m0 + mi * 16 + (lane & 15)) * ROWB +
                               (kk * 2 + (lane >> 4)) * 16);
                ldsm4(a[mi][0], a[mi][1], a[mi][2], a[mi][3], ad);
            }
            uint32_t bh[4][2], bl[4][2];
#pragma unroll
            for (int np = 0; np < 2; np++) {      // 2 n8-frags per ldsm4
                const int rb = n0 + np * 16 + (lane & 7) + ((lane >> 4) << 3);
                const int ch = kk * 2 + ((lane >> 3) & 1);
                const uint32_t ad = base + MATB +
                    (uint32_t)(rb * ROWB + ch * 16);
                ldsm4(bh[np*2][0], bh[np*2][1], bh[np*2+1][0], bh[np*2+1][1], ad);
                ldsm4(bl[np*2][0], bl[np*2][1], bl[np*2+1][0], bl[np*2+1][1],
                      ad + MATB);
            }
#pragma unroll
            for (int mi = 0; mi < 4; mi++)
#pragma unroll
                for (int ni = 0; ni < 4; ni++) {
                    mma16816(acc[mi][ni], a[mi], bh[ni]);
                    mma16816(acc[mi][ni], a[mi], bl[ni]);
                }
        }
        __syncthreads();
    }

    // epilogue: c-frag layout -> direct f32 stores
    const int er = lane >> 2;
    const int ec = (lane & 3) * 2;
#pragma unroll
    for (int mi = 0; mi < 4; mi++) {
        const int r = row0 + m0 + mi * 16 + er;
#pragma unroll
        for (int ni = 0; ni < 4; ni++) {
            const int cc = col0 + n0 + ni * 8 + ec;
            *(float2*)&C[(size_t)r * N + cc] =
                make_float2(acc[mi][ni][0], acc[mi][ni][1]);
            *(float2*)&C[(size_t)(r + 8) * N + cc] =
                make_float2(acc[mi][ni][2], acc[mi][ni][3]);
        }
    }
}

// ---------------- conversions ------------------------------------------------
__global__ void __launch_bounds__(256) conv_single(
    const float* __restrict__ in, h16* __restrict__ o, int n4)
{
    int i = blockIdx.x * 256 + threadIdx.x;
    if (i >= n4) return;
    float4 v = ((const float4*)in)[i];
    __half2 p0 = __floats2half2_rn(v.x, v.y);
    __half2 p1 = __floats2half2_rn(v.z, v.w);
    uint2 u;
    u.x = *(uint32_t*)&p0;
    u.y = *(uint32_t*)&p1;
    ((uint2*)o)[i] = u;
}

__global__ void __launch_bounds__(256) conv_pair(
    const float* __restrict__ in, h16* __restrict__ oh, h16* __restrict__ ol,
    int n4)
{
    int i = blockIdx.x * 256 + threadIdx.x;
    if (i >= n4) return;
    float4 v = ((const float4*)in)[i];
    float vv[4] = {v.x, v.y, v.z, v.w};
    h16 hh[4], ll[4];
#pragma unroll
    for (int j = 0; j < 4; j++) {
        h16 h = __float2half_rn(vv[j]);
        hh[j] = h;
        ll[j] = __float2half_rn(vv[j] - __half2float(h));
    }
    ((uint2*)oh)[i] = *(uint2*)hh;
    ((uint2*)ol)[i] = *(uint2*)ll;
}

// vt[b][d][t] = v[b][t][d], split to hi/lo fp16
__global__ void __launch_bounds__(256) transpose_pair(
    const float* __restrict__ v, h16* __restrict__ th, h16* __restrict__ tl)
{
    __shared__ float tile[32][33];
    const int b  = blockIdx.z;
    const int d0 = blockIdx.x * 32;
    const int t0 = blockIdx.y * 32;
    const float* vb = v + (size_t)b * Tsz * Dsz;
    const int tx = threadIdx.x, ty = threadIdx.y;
#pragma unroll
    for (int j = ty; j < 32; j += 8)
        tile[j][tx] = vb[(size_t)(t0 + j) * Dsz + d0 + tx];
    __syncthreads();
    h16* oh = th + (size_t)b * Dsz * Tsz;
    h16* ol = tl + (size_t)b * Dsz * Tsz;
#pragma unroll
    for (int j = ty; j < 32; j += 8) {
        float val = tile[tx][j];
        h16 h = __float2half_rn(val);
        oh[(size_t)(d0 + j) * Tsz + t0 + tx] = h;
        ol[(size_t)(d0 + j) * Tsz + t0 + tx] =
            __float2half_rn(val - __half2float(h));
    }
}

// ---------------- causal softmax -> fp16 P (zero tail to 128 boundary) ------
__device__ __forceinline__ float warp_max_f(float v) {
#pragma unroll
    for (int o = 16; o; o >>= 1) v = fmaxf(v, __shfl_xor_sync(0xffffffffu, v, o));
    return v;
}
__device__ __forceinline__ float warp_sum_f(float v) {
#pragma unroll
    for (int o = 16; o; o >>= 1) v += __shfl_xor_sync(0xffffffffu, v, o);
    return v;
}

__global__ void __launch_bounds__(256) softmax_pf(
    const float* __restrict__ S, h16* __restrict__ pf)
{
    __shared__ float es[Tsz];
    __shared__ float red[8];
    const int b = blockIdx.y;
    const int r = blockIdx.x;
    const float* row = S + ((size_t)b * Tsz + r) * Tsz;
    h16* pr = pf + ((size_t)b * Tsz + r) * Tsz;
    const int len = r + 1;
    const int blk_end = ((r >> 7) + 1) << 7;
    const float scale = 0.03125f;  // 1/sqrt(1024)
    const int tid = threadIdx.x;

    float m = -INFINITY;
    for (int i = tid; i < len; i += 256) m = fmaxf(m, row[i]);
    m = warp_max_f(m);
    if ((tid & 31) == 0) red[tid >> 5] = m;
    __syncthreads();
    m = red[0];
#pragma unroll
    for (int i = 1; i < 8; i++) m = fmaxf(m, red[i]);
    __syncthreads();

    float ssum = 0.f;
    for (int i = tid; i < len; i += 256) {
        float e = __expf((row[i] - m) * scale);
        es[i] = e;
        ssum += e;
    }
    ssum = warp_sum_f(ssum);
    if ((tid & 31) == 0) red[tid >> 5] = ssum;
    __syncthreads();
    ssum = 0.f;
#pragma unroll
    for (int i = 0; i < 8; i++) ssum += red[i];
    const float inv = 1.f / ssum;
    __syncthreads();

    for (int i = tid; i < len; i += 256)
        pr[i] = __float2half_rn(es[i] * inv);
    for (int i = len + tid; i < blk_end; i += 256)
        pr[i] = __float2half_rn(0.f);
}

// ---------------- launch ------------------------------------------------------
extern "C" void kernel_launch(void* const* d_in, const int* in_sizes, int n_in,
                              void* d_out, int out_size)
{
    (void)in_sizes; (void)n_in; (void)out_size;
    const float* x = (const float*)d_in[0];
    const float* W[3] = {(const float*)d_in[1], (const float*)d_in[2],
                         (const float*)d_in[3]};
    float* out = (float*)d_out;

    float *q, *k, *v, *s;
    h16 *xf, *wh, *wl, *qf, *kh, *kl, *vth, *vtl, *pf;
    cudaGetSymbolAddress((void**)&q,   g_q);
    cudaGetSymbolAddress((void**)&k,   g_k);
    cudaGetSymbolAddress((void**)&v,   g_v);
    cudaGetSymbolAddress((void**)&s,   g_s);
    cudaGetSymbolAddress((void**)&xf,  g_xf);
    cudaGetSymbolAddress((void**)&wh,  g_wh);
    cudaGetSymbolAddress((void**)&wl,  g_wl);
    cudaGetSymbolAddress((void**)&qf,  g_qf);
    cudaGetSymbolAddress((void**)&kh,  g_kh);
    cudaGetSymbolAddress((void**)&kl,  g_kl);
    cudaGetSymbolAddress((void**)&vth, g_vth);
    cudaGetSymbolAddress((void**)&vtl, g_vtl);
    cudaGetSymbolAddress((void**)&pf,  g_pf);

    cudaFuncSetAttribute(hgemm_nt, cudaFuncAttributeMaxDynamicSharedMemorySize,
                         SMEMB);

    const int nX = BT * Dsz;    // 8M
    const int nW = Dsz * Dsz;   // 1M

    // input conversions
    conv_single<<<nX / 4 / 256, 256>>>(x, xf, nX / 4);
    for (int i = 0; i < 3; i++)
        conv_pair<<<nW / 4 / 256, 256>>>(W[i], wh + (size_t)i * nW,
                                         wl + (size_t)i * nW, nW / 4);

    // QKV projections: [8192,1024] = x @ W^T
    dim3 gq(Dsz / 128, BT / 128, 1);
    hgemm_nt<<<gq, 256, SMEMB>>>(xf, wh,                 wl,                 q,
                                 Dsz, Dsz, 0, 0, 0, 0);
    hgemm_nt<<<gq, 256, SMEMB>>>(xf, wh + (size_t)nW,    wl + (size_t)nW,    k,
                                 Dsz, Dsz, 0, 0, 0, 0);
    hgemm_nt<<<gq, 256, SMEMB>>>(xf, wh + (size_t)2*nW,  wl + (size_t)2*nW,  v,
                                 Dsz, Dsz, 0, 0, 0, 0);

    // re-quantize activations for the attention GEMMs
    conv_single<<<nX / 4 / 256, 256>>>(q, qf, nX / 4);
    conv_pair  <<<nX / 4 / 256, 256>>>(k, kh, kl, nX / 4);
    transpose_pair<<<dim3(Dsz / 32, Tsz / 32, Bsz), dim3(32, 8)>>>(v, vth, vtl);

    // S = Q @ K^T per batch (causal tile skip)
    hgemm_nt<<<dim3(Tsz / 128, Tsz / 128, Bsz), 256, SMEMB>>>(
        qf, kh, kl, s, Tsz, Dsz, 1,
        (long long)Tsz * Dsz, (long long)Tsz * Dsz, (long long)Tsz * Tsz);

    // causal softmax -> P fp16 (tail zero-filled to 128 boundary)
    softmax_pf<<<dim3(Tsz, Bsz), 256>>>(s, pf);

    // O = P @ V   (NT against V^T, K clipped to row0+128)
    hgemm_nt<<<dim3(Dsz / 128, Tsz / 128, Bsz), 256, SMEMB>>>(
        pf, vth, vtl, out, Dsz, Tsz, 2,
        (long long)Tsz * Tsz, (long long)Dsz * Tsz, (long long)Tsz * Dsz);
}

// round 4
// speedup vs baseline: 6.7784x; 1.7852x over previous
#include <cuda_runtime.h>
#include <cuda_fp16.h>
#include <stdint.h>
#include <math.h>

#define Bsz 4
#define Tsz 2048
#define Dsz 1024
#define BT  (Bsz * Tsz)

typedef __half h16;

// ---------------- scratch (__device__ globals; allocation-free rule) -------
__device__ __align__(16) float g_s[(size_t)Bsz * Tsz * Tsz];
__device__ __align__(16) h16 g_xf[(size_t)BT * Dsz];
__device__ __align__(16) h16 g_wf[3][(size_t)Dsz * Dsz];
__device__ __align__(16) h16 g_qf[(size_t)BT * Dsz];
__device__ __align__(16) h16 g_kf[(size_t)BT * Dsz];
__device__ __align__(16) h16 g_vf[(size_t)BT * Dsz];
__device__ __align__(16) h16 g_vt[(size_t)BT * Dsz];
__device__ __align__(16) h16 g_pf[(size_t)Bsz * Tsz * Tsz];

// ---------------- low-level helpers (plain sm_80-era PTX only) --------------
__device__ __forceinline__ uint32_t smem_u32(const void* p) {
    uint32_t a;
    asm("{ .reg .u64 t; cvta.to.shared.u64 t, %1; cvt.u32.u64 %0, t; }"
        : "=r"(a) : "l"(p));
    return a;
}

#define CP_ASYNC16(dst, src) \
    asm volatile("cp.async.cg.shared.global [%0], [%1], 16;" \
                 :: "r"(dst), "l"(src))
#define CP_COMMIT() asm volatile("cp.async.commit_group;")
#define CP_WAIT1()  asm volatile("cp.async.wait_group 1;")

__device__ __forceinline__ void ldsm4(uint32_t& r0, uint32_t& r1,
                                      uint32_t& r2, uint32_t& r3,
                                      uint32_t addr) {
    asm volatile("ldmatrix.sync.aligned.m8n8.x4.shared.b16 {%0,%1,%2,%3}, [%4];"
                 : "=r"(r0), "=r"(r1), "=r"(r2), "=r"(r3) : "r"(addr));
}

__device__ __forceinline__ void mma16816(float* d, const uint32_t* a,
                                         const uint32_t* b) {
    asm volatile(
        "mma.sync.aligned.m16n8k16.row.col.f32.f16.f16.f32 "
        "{%0,%1,%2,%3}, {%4,%5,%6,%7}, {%8,%9}, {%0,%1,%2,%3};"
        : "+f"(d[0]), "+f"(d[1]), "+f"(d[2]), "+f"(d[3])
        : "r"(a[0]), "r"(a[1]), "r"(a[2]), "r"(a[3]), "r"(b[0]), "r"(b[1]));
}

// ---------------- HMMA NT GEMM: C[M,N] = A[M,K] * B[N,K]^T ------------------
// Single fp16 operands, fp32 accumulate.
// mode 0: full.  mode 1: causal tile skip.  mode 2: kend = row0+128.
// ofp16: write C as fp16 (else fp32).
#define KC    64
#define ROWB  144                // 128B data + 16B pad per smem row
#define MATB  (128 * ROWB)       // 18432 B per matrix tile
#define STGB  (2 * MATB)         // A, B
#define SMEMB (2 * STGB)         // double buffered: 73728 B

__global__ void __launch_bounds__(256) hgemm_nt(
    const h16* __restrict__ Af, const h16* __restrict__ Bf,
    void* __restrict__ Cv, int N, int K, int mode, int ofp16,
    long long sA, long long sB, long long sC)
{
    const int bz = blockIdx.z;
    Af += (size_t)bz * sA;
    Bf += (size_t)bz * sB;

    const int row0 = blockIdx.y * 128;
    const int col0 = blockIdx.x * 128;
    if (mode == 1 && col0 >= row0 + 128) return;
    const int kend = (mode == 2) ? (row0 + 128) : K;
    const int nc = kend / KC;

    extern __shared__ char smc[];
    const uint32_t smb = smem_u32(smc);
    const int tid  = threadIdx.x;
    const int lane = tid & 31;
    const int wid  = tid >> 5;
    const int m0 = (wid & 1) * 64;     // warp tile 64x32, warps 2x4
    const int n0 = (wid >> 1) * 32;

    float acc[4][4][4];
#pragma unroll
    for (int i = 0; i < 4; i++)
#pragma unroll
        for (int j = 0; j < 4; j++)
#pragma unroll
            for (int q = 0; q < 4; q++) acc[i][j][q] = 0.f;

    const int lch = tid & 7;       // 16B chunk within 128B row
    const int lr0 = tid >> 3;      // 0..31

    auto do_load = [&](int st, int k0) {
        const uint32_t sb = smb + (uint32_t)st * STGB;
        const h16* pA = Af + (size_t)row0 * K + k0;
        const h16* pB = Bf + (size_t)col0 * K + k0;
#pragma unroll
        for (int j = 0; j < 4; j++) {
            const int row = lr0 + j * 32;
            const size_t go = (size_t)row * K + lch * 8;
            const uint32_t so = sb + (uint32_t)(row * ROWB + lch * 16);
            CP_ASYNC16(so,        pA + go);
            CP_ASYNC16(so + MATB, pB + go);
        }
    };

    do_load(0, 0);
    CP_COMMIT();

    for (int c = 0; c < nc; c++) {
        if (c + 1 < nc) do_load((c + 1) & 1, (c + 1) * KC);
        CP_COMMIT();
        CP_WAIT1();
        __syncthreads();

        const uint32_t base = smb + (uint32_t)(c & 1) * STGB;
#pragma unroll
        for (int kk = 0; kk < 4; kk++) {          // four k16 steps per KC=64
            uint32_t a[4][4];
#pragma unroll
            for (int mi = 0; mi < 4; mi++) {
                const uint32_t ad = base +
                    (uint32_t)((m0 + mi * 16 + (lane & 15)) * ROWB +
                               (kk * 2 + (lane >> 4)) * 16);
                ldsm4(a[mi][0], a[mi][1], a[mi][2], a[mi][3], ad);
            }
            uint32_t bb[4][2];
#pragma unroll
            for (int np = 0; np < 2; np++) {      // 2 n8-frags per ldsm4
                const int rb = n0 + np * 16 + (lane & 7) + ((lane >> 4) << 3);
                const int ch = kk * 2 + ((lane >> 3) & 1);
                const uint32_t ad = base + MATB +
                    (uint32_t)(rb * ROWB + ch * 16);
                ldsm4(bb[np*2][0], bb[np*2][1], bb[np*2+1][0], bb[np*2+1][1], ad);
            }
#pragma unroll
            for (int mi = 0; mi < 4; mi++)
#pragma unroll
                for (int ni = 0; ni < 4; ni++)
                    mma16816(acc[mi][ni], a[mi], bb[ni]);
        }
        __syncthreads();
    }

    // epilogue
    const int er = lane >> 2;
    const int ec = (lane & 3) * 2;
    if (!ofp16) {
        float* C = (float*)Cv + (size_t)bz * sC;
#pragma unroll
        for (int mi = 0; mi < 4; mi++) {
            const int r = row0 + m0 + mi * 16 + er;
#pragma unroll
            for (int ni = 0; ni < 4; ni++) {
                const int cc = col0 + n0 + ni * 8 + ec;
                *(float2*)&C[(size_t)r * N + cc] =
                    make_float2(acc[mi][ni][0], acc[mi][ni][1]);
                *(float2*)&C[(size_t)(r + 8) * N + cc] =
                    make_float2(acc[mi][ni][2], acc[mi][ni][3]);
            }
        }
    } else {
        h16* C = (h16*)Cv + (size_t)bz * sC;
#pragma unroll
        for (int mi = 0; mi < 4; mi++) {
            const int r = row0 + m0 + mi * 16 + er;
#pragma unroll
            for (int ni = 0; ni < 4; ni++) {
                const int cc = col0 + n0 + ni * 8 + ec;
                __half2 h0 = __floats2half2_rn(acc[mi][ni][0], acc[mi][ni][1]);
                __half2 h1 = __floats2half2_rn(acc[mi][ni][2], acc[mi][ni][3]);
                *(__half2*)&C[(size_t)r * N + cc] = h0;
                *(__half2*)&C[(size_t)(r + 8) * N + cc] = h1;
            }
        }
    }
}

// ---------------- conversions ------------------------------------------------
__global__ void __launch_bounds__(256) conv_single(
    const float* __restrict__ in, h16* __restrict__ o, int n4)
{
    int i = blockIdx.x * 256 + threadIdx.x;
    if (i >= n4) return;
    float4 v = ((const float4*)in)[i];
    __half2 p0 = __floats2half2_rn(v.x, v.y);
    __half2 p1 = __floats2half2_rn(v.z, v.w);
    uint2 u;
    u.x = *(uint32_t*)&p0;
    u.y = *(uint32_t*)&p1;
    ((uint2*)o)[i] = u;
}

// vt[b][d][t] = v[b][t][d]  (fp16 -> fp16)
__global__ void __launch_bounds__(256) transpose_h(
    const h16* __restrict__ v, h16* __restrict__ vt)
{
    __shared__ h16 tile[32][40];
    const int b  = blockIdx.z;
    const int d0 = blockIdx.x * 32;
    const int t0 = blockIdx.y * 32;
    const h16* vb = v + (size_t)b * Tsz * Dsz;
    const int tx = threadIdx.x, ty = threadIdx.y;
#pragma unroll
    for (int j = ty; j < 32; j += 8)
        tile[j][tx] = vb[(size_t)(t0 + j) * Dsz + d0 + tx];
    __syncthreads();
    h16* o = vt + (size_t)b * Dsz * Tsz;
#pragma unroll
    for (int j = ty; j < 32; j += 8)
        o[(size_t)(d0 + j) * Tsz + t0 + tx] = tile[tx][j];
}

// ---------------- causal softmax -> fp16 P (zero tail to 128 boundary) ------
__device__ __forceinline__ float warp_max_f(float v) {
#pragma unroll
    for (int o = 16; o; o >>= 1) v = fmaxf(v, __shfl_xor_sync(0xffffffffu, v, o));
    return v;
}
__device__ __forceinline__ float warp_sum_f(float v) {
#pragma unroll
    for (int o = 16; o; o >>= 1) v += __shfl_xor_sync(0xffffffffu, v, o);
    return v;
}

__global__ void __launch_bounds__(256) softmax_pf(
    const float* __restrict__ S, h16* __restrict__ pf)
{
    __shared__ float es[Tsz];
    __shared__ float red[8];
    const int b = blockIdx.y;
    const int r = blockIdx.x;
    const float* row = S + ((size_t)b * Tsz + r) * Tsz;
    h16* pr = pf + ((size_t)b * Tsz + r) * Tsz;
    const int len = r + 1;
    const int blk_end = ((r >> 7) + 1) << 7;
    const float scale = 0.03125f;  // 1/sqrt(1024)
    const int tid = threadIdx.x;

    float m = -INFINITY;
    for (int i = tid; i < len; i += 256) m = fmaxf(m, row[i]);
    m = warp_max_f(m);
    if ((tid & 31) == 0) red[tid >> 5] = m;
    __syncthreads();
    m = red[0];
#pragma unroll
    for (int i = 1; i < 8; i++) m = fmaxf(m, red[i]);
    __syncthreads();

    float ssum = 0.f;
    for (int i = tid; i < len; i += 256) {
        float e = __expf((row[i] - m) * scale);
        es[i] = e;
        ssum += e;
    }
    ssum = warp_sum_f(ssum);
    if ((tid & 31) == 0) red[tid >> 5] = ssum;
    __syncthreads();
    ssum = 0.f;
#pragma unroll
    for (int i = 0; i < 8; i++) ssum += red[i];
    const float inv = 1.f / ssum;
    __syncthreads();

    for (int i = tid; i < len; i += 256)
        pr[i] = __float2half_rn(es[i] * inv);
    for (int i = len + tid; i < blk_end; i += 256)
        pr[i] = __float2half_rn(0.f);
}

// ---------------- launch ------------------------------------------------------
extern "C" void kernel_launch(void* const* d_in, const int* in_sizes, int n_in,
                              void* d_out, int out_size)
{
    (void)in_sizes; (void)n_in; (void)out_size;
    const float* x = (const float*)d_in[0];
    const float* W[3] = {(const float*)d_in[1], (const float*)d_in[2],
                         (const float*)d_in[3]};
    float* out = (float*)d_out;

    float* s;
    h16 *xf, *wf, *qf, *kf, *vf, *vt, *pf;
    cudaGetSymbolAddress((void**)&s,  g_s);
    cudaGetSymbolAddress((void**)&xf, g_xf);
    cudaGetSymbolAddress((void**)&wf, g_wf);
    cudaGetSymbolAddress((void**)&qf, g_qf);
    cudaGetSymbolAddress((void**)&kf, g_kf);
    cudaGetSymbolAddress((void**)&vf, g_vf);
    cudaGetSymbolAddress((void**)&vt, g_vt);
    cudaGetSymbolAddress((void**)&pf, g_pf);

    cudaFuncSetAttribute(hgemm_nt, cudaFuncAttributeMaxDynamicSharedMemorySize,
                         SMEMB);

    const int nX = BT * Dsz;    // 8M
    const int nW = Dsz * Dsz;   // 1M

    // input conversions (single fp16)
    conv_single<<<nX / 4 / 256, 256>>>(x, xf, nX / 4);
    for (int i = 0; i < 3; i++)
        conv_single<<<nW / 4 / 256, 256>>>(W[i], wf + (size_t)i * nW, nW / 4);

    // QKV projections, writing fp16 activations directly
    dim3 gq(Dsz / 128, BT / 128, 1);
    hgemm_nt<<<gq, 256, SMEMB>>>(xf, wf,                 qf, Dsz, Dsz, 0, 1,
                                 0, 0, 0);
    hgemm_nt<<<gq, 256, SMEMB>>>(xf, wf + (size_t)nW,    kf, Dsz, Dsz, 0, 1,
                                 0, 0, 0);
    hgemm_nt<<<gq, 256, SMEMB>>>(xf, wf + (size_t)2*nW,  vf, Dsz, Dsz, 0, 1,
                                 0, 0, 0);

    // V transpose (fp16)
    transpose_h<<<dim3(Dsz / 32, Tsz / 32, Bsz), dim3(32, 8)>>>(vf, vt);

    // S = Q @ K^T per batch (causal tile skip), fp32 scores
    hgemm_nt<<<dim3(Tsz / 128, Tsz / 128, Bsz), 256, SMEMB>>>(
        qf, kf, s, Tsz, Dsz, 1, 0,
        (long long)Tsz * Dsz, (long long)Tsz * Dsz, (long long)Tsz * Tsz);

    // causal softmax -> P fp16 (tail zero-filled to 128 boundary)
    softmax_pf<<<dim3(Tsz, Bsz), 256>>>(s, pf);

    // O = P @ V   (NT against V^T, K clipped to row0+128), fp32 out
    hgemm_nt<<<dim3(Dsz / 128, Tsz / 128, Bsz), 256, SMEMB>>>(
        pf, vt, out, Dsz, Tsz, 2, 0,
        (long long)Tsz * Tsz, (long long)Dsz * Tsz, (long long)Tsz * Dsz);
}

// round 5
// speedup vs baseline: 7.4453x; 1.0984x over previous
#include <cuda_runtime.h>
#include <cuda_fp16.h>
#include <stdint.h>
#include <math.h>

#define Bsz 4
#define Tsz 2048
#define Dsz 1024
#define BT  (Bsz * Tsz)

typedef __half h16;

// ---------------- scratch (__device__ globals; allocation-free rule) -------
__device__ __align__(16) float g_s[(size_t)Bsz * Tsz * Tsz];
__device__ __align__(16) h16 g_xf[(size_t)BT * Dsz];
__device__ __align__(16) h16 g_wf[3][(size_t)Dsz * Dsz];   // contiguous [3072,1024]
__device__ __align__(16) h16 g_qkv[(size_t)BT * 3 * Dsz];  // [8192, 3072] fp16
__device__ __align__(16) h16 g_vt[(size_t)BT * Dsz];
__device__ __align__(16) h16 g_pf[(size_t)Bsz * Tsz * Tsz];

// ---------------- low-level helpers (plain sm_80-era PTX only) --------------
__device__ __forceinline__ uint32_t smem_u32(const void* p) {
    uint32_t a;
    asm("{ .reg .u64 t; cvta.to.shared.u64 t, %1; cvt.u32.u64 %0, t; }"
        : "=r"(a) : "l"(p));
    return a;
}

#define CP_ASYNC16(dst, src) \
    asm volatile("cp.async.cg.shared.global [%0], [%1], 16;" \
                 :: "r"(dst), "l"(src))
#define CP_COMMIT() asm volatile("cp.async.commit_group;")
#define CP_WAIT1()  asm volatile("cp.async.wait_group 1;")

__device__ __forceinline__ void ldsm4(uint32_t& r0, uint32_t& r1,
                                      uint32_t& r2, uint32_t& r3,
                                      uint32_t addr) {
    asm volatile("ldmatrix.sync.aligned.m8n8.x4.shared.b16 {%0,%1,%2,%3}, [%4];"
                 : "=r"(r0), "=r"(r1), "=r"(r2), "=r"(r3) : "r"(addr));
}

__device__ __forceinline__ void mma16816(float* d, const uint32_t* a,
                                         const uint32_t* b) {
    asm volatile(
        "mma.sync.aligned.m16n8k16.row.col.f32.f16.f16.f32 "
        "{%0,%1,%2,%3}, {%4,%5,%6,%7}, {%8,%9}, {%0,%1,%2,%3};"
        : "+f"(d[0]), "+f"(d[1]), "+f"(d[2]), "+f"(d[3])
        : "r"(a[0]), "r"(a[1]), "r"(a[2]), "r"(a[3]), "r"(b[0]), "r"(b[1]));
}

// ---------------- HMMA NT GEMM: C[M,N] = A[M,K] * B[N,K]^T ------------------
// fp16 operands, fp32 accumulate. lda/ldb/ldc row strides (elements).
// mode 0: full.  mode 1: causal tile skip (+reversed row order).
// mode 2: kend = row0+128 (+reversed row order).
// ofp16: write C as fp16 (else fp32).
#define KC    64
#define ROWB  144                // 128B data + 16B pad per smem row
#define MATB  (128 * ROWB)       // 18432 B per matrix tile
#define STGB  (2 * MATB)         // A, B
#define NSTG  3
#define SMEMB (NSTG * STGB)      // 110592 B

__global__ void __launch_bounds__(256, 2) hgemm_nt(
    const h16* __restrict__ Af, const h16* __restrict__ Bf,
    void* __restrict__ Cv, int K, int lda, int ldb, int ldc,
    int mode, int ofp16, long long sA, long long sB, long long sC)
{
    const int bz = blockIdx.z;
    Af += (size_t)bz * sA;
    Bf += (size_t)bz * sB;

    const int by = mode ? ((int)gridDim.y - 1 - (int)blockIdx.y)
                        : (int)blockIdx.y;
    const int row0 = by * 128;
    const int col0 = blockIdx.x * 128;
    if (mode == 1 && col0 >= row0 + 128) return;
    const int kend = (mode == 2) ? (row0 + 128) : K;
    const int nc = kend / KC;           // >= 2 always (min kend 128)

    extern __shared__ char smc[];
    const uint32_t smb = smem_u32(smc);
    const int tid  = threadIdx.x;
    const int lane = tid & 31;
    const int wid  = tid >> 5;
    const int m0 = (wid & 1) * 64;      // warp tile 64x32, warps 2x4
    const int n0 = (wid >> 1) * 32;

    float acc[4][4][4];
#pragma unroll
    for (int i = 0; i < 4; i++)
#pragma unroll
        for (int j = 0; j < 4; j++)
#pragma unroll
            for (int q = 0; q < 4; q++) acc[i][j][q] = 0.f;

    const int lch = tid & 7;       // 16B chunk within 128B row
    const int lr0 = tid >> 3;      // 0..31

    auto do_load = [&](int st, int k0) {
        const uint32_t sb = smb + (uint32_t)st * STGB;
        const h16* pA = Af + (size_t)row0 * lda + k0;
        const h16* pB = Bf + (size_t)col0 * ldb + k0;
#pragma unroll
        for (int j = 0; j < 4; j++) {
            const int row = lr0 + j * 32;
            const uint32_t so = sb + (uint32_t)(row * ROWB + lch * 16);
            CP_ASYNC16(so,        pA + (size_t)row * lda + lch * 8);
            CP_ASYNC16(so + MATB, pB + (size_t)row * ldb + lch * 8);
        }
    };

    do_load(0, 0);
    CP_COMMIT();
    do_load(1, KC);
    CP_COMMIT();

    for (int c = 0; c < nc; c++) {
        CP_WAIT1();                      // stage c resident
        __syncthreads();                 // all warps done with stage (c+2)%3
        if (c + 2 < nc) do_load((c + 2) % NSTG, (c + 2) * KC);
        CP_COMMIT();

        const uint32_t base = smb + (uint32_t)(c % NSTG) * STGB;
#pragma unroll
        for (int kk = 0; kk < 4; kk++) {          // four k16 steps per KC=64
            uint32_t a[4][4];
#pragma unroll
            for (int mi = 0; mi < 4; mi++) {
                const uint32_t ad = base +
                    (uint32_t)((m0 + mi * 16 + (lane & 15)) * ROWB +
                               (kk * 2 + (lane >> 4)) * 16);
                ldsm4(a[mi][0], a[mi][1], a[mi][2], a[mi][3], ad);
            }
            uint32_t bb[4][2];
#pragma unroll
            for (int np = 0; np < 2; np++) {      // 2 n8-frags per ldsm4
                const int rb = n0 + np * 16 + (lane & 7) + ((lane >> 4) << 3);
                const int ch = kk * 2 + ((lane >> 3) & 1);
                const uint32_t ad = base + MATB +
                    (uint32_t)(rb * ROWB + ch * 16);
                ldsm4(bb[np*2][0], bb[np*2][1], bb[np*2+1][0], bb[np*2+1][1], ad);
            }
#pragma unroll
            for (int mi = 0; mi < 4; mi++)
#pragma unroll
                for (int ni = 0; ni < 4; ni++)
                    mma16816(acc[mi][ni], a[mi], bb[ni]);
        }
    }

    // epilogue
    const int er = lane >> 2;
    const int ec = (lane & 3) * 2;
    if (!ofp16) {
        float* C = (float*)Cv + (size_t)bz * sC;
#pragma unroll
        for (int mi = 0; mi < 4; mi++) {
            const int r = row0 + m0 + mi * 16 + er;
#pragma unroll
            for (int ni = 0; ni < 4; ni++) {
                const int cc = col0 + n0 + ni * 8 + ec;
                *(float2*)&C[(size_t)r * ldc + cc] =
                    make_float2(acc[mi][ni][0], acc[mi][ni][1]);
                *(float2*)&C[(size_t)(r + 8) * ldc + cc] =
                    make_float2(acc[mi][ni][2], acc[mi][ni][3]);
            }
        }
    } else {
        h16* C = (h16*)Cv + (size_t)bz * sC;
#pragma unroll
        for (int mi = 0; mi < 4; mi++) {
            const int r = row0 + m0 + mi * 16 + er;
#pragma unroll
            for (int ni = 0; ni < 4; ni++) {
                const int cc = col0 + n0 + ni * 8 + ec;
                __half2 h0 = __floats2half2_rn(acc[mi][ni][0], acc[mi][ni][1]);
                __half2 h1 = __floats2half2_rn(acc[mi][ni][2], acc[mi][ni][3]);
                *(__half2*)&C[(size_t)r * ldc + cc] = h0;
                *(__half2*)&C[(size_t)(r + 8) * ldc + cc] = h1;
            }
        }
    }
}

// ---------------- conversions ------------------------------------------------
__global__ void __launch_bounds__(256) conv_single(
    const float* __restrict__ in, h16* __restrict__ o, int n4)
{
    int i = blockIdx.x * 256 + threadIdx.x;
    if (i >= n4) return;
    float4 v = ((const float4*)in)[i];
    __half2 p0 = __floats2half2_rn(v.x, v.y);
    __half2 p1 = __floats2half2_rn(v.z, v.w);
    uint2 u;
    u.x = *(uint32_t*)&p0;
    u.y = *(uint32_t*)&p1;
    ((uint2*)o)[i] = u;
}

// all three weight matrices in one launch
__global__ void __launch_bounds__(256) conv_w3(
    const float* __restrict__ w0, const float* __restrict__ w1,
    const float* __restrict__ w2, h16* __restrict__ o, int n4each)
{
    int i = blockIdx.x * 256 + threadIdx.x;
    if (i >= 3 * n4each) return;
    const int m = i / n4each;
    const int r = i - m * n4each;
    const float* in = (m == 0) ? w0 : (m == 1) ? w1 : w2;
    float4 v = ((const float4*)in)[r];
    __half2 p0 = __floats2half2_rn(v.x, v.y);
    __half2 p1 = __floats2half2_rn(v.z, v.w);
    uint2 u;
    u.x = *(uint32_t*)&p0;
    u.y = *(uint32_t*)&p1;
    ((uint2*)o)[i] = u;
}

// vt[b][d][t] = v[b][t][d]  (fp16 -> fp16, source row stride ldv)
__global__ void __launch_bounds__(256) transpose_h(
    const h16* __restrict__ v, h16* __restrict__ vt, int ldv)
{
    __shared__ h16 tile[32][40];
    const int b  = blockIdx.z;
    const int d0 = blockIdx.x * 32;
    const int t0 = blockIdx.y * 32;
    const h16* vb = v + (size_t)b * Tsz * ldv;
    const int tx = threadIdx.x, ty = threadIdx.y;
#pragma unroll
    for (int j = ty; j < 32; j += 8)
        tile[j][tx] = vb[(size_t)(t0 + j) * ldv + d0 + tx];
    __syncthreads();
    h16* o = vt + (size_t)b * Dsz * Tsz;
#pragma unroll
    for (int j = ty; j < 32; j += 8)
        o[(size_t)(d0 + j) * Tsz + t0 + tx] = tile[tx][j];
}

// ---------------- causal softmax -> fp16 P (zero tail to 128 boundary) ------
__device__ __forceinline__ float warp_max_f(float v) {
#pragma unroll
    for (int o = 16; o; o >>= 1) v = fmaxf(v, __shfl_xor_sync(0xffffffffu, v, o));
    return v;
}
__device__ __forceinline__ float warp_sum_f(float v) {
#pragma unroll
    for (int o = 16; o; o >>= 1) v += __shfl_xor_sync(0xffffffffu, v, o);
    return v;
}

__global__ void __launch_bounds__(256) softmax_pf(
    const float* __restrict__ S, h16* __restrict__ pf)
{
    __shared__ float es[Tsz];
    __shared__ float red[8];
    const int b = blockIdx.y;
    const int r = blockIdx.x;
    const float* row = S + ((size_t)b * Tsz + r) * Tsz;
    h16* pr = pf + ((size_t)b * Tsz + r) * Tsz;
    const int len = r + 1;
    const int blk_end = ((r >> 7) + 1) << 7;
    const float scale = 0.03125f;  // 1/sqrt(1024)
    const int tid = threadIdx.x;

    float m = -INFINITY;
    for (int i = tid; i < len; i += 256) m = fmaxf(m, row[i]);
    m = warp_max_f(m);
    if ((tid & 31) == 0) red[tid >> 5] = m;
    __syncthreads();
    m = red[0];
#pragma unroll
    for (int i = 1; i < 8; i++) m = fmaxf(m, red[i]);
    __syncthreads();

    float ssum = 0.f;
    for (int i = tid; i < len; i += 256) {
        float e = __expf((row[i] - m) * scale);
        es[i] = e;
        ssum += e;
    }
    ssum = warp_sum_f(ssum);
    if ((tid & 31) == 0) red[tid >> 5] = ssum;
    __syncthreads();
    ssum = 0.f;
#pragma unroll
    for (int i = 0; i < 8; i++) ssum += red[i];
    const float inv = 1.f / ssum;
    __syncthreads();

    for (int i = tid; i < len; i += 256)
        pr[i] = __float2half_rn(es[i] * inv);
    for (int i = len + tid; i < blk_end; i += 256)
        pr[i] = __float2half_rn(0.f);
}

// ---------------- launch ------------------------------------------------------
extern "C" void kernel_launch(void* const* d_in, const int* in_sizes, int n_in,
                              void* d_out, int out_size)
{
    (void)in_sizes; (void)n_in; (void)out_size;
    const float* x = (const float*)d_in[0];
    float* out = (float*)d_out;

    float* s;
    h16 *xf, *wf, *qkv, *vt, *pf;
    cudaGetSymbolAddress((void**)&s,   g_s);
    cudaGetSymbolAddress((void**)&xf,  g_xf);
    cudaGetSymbolAddress((void**)&wf,  g_wf);
    cudaGetSymbolAddress((void**)&qkv, g_qkv);
    cudaGetSymbolAddress((void**)&vt,  g_vt);
    cudaGetSymbolAddress((void**)&pf,  g_pf);

    cudaFuncSetAttribute(hgemm_nt, cudaFuncAttributeMaxDynamicSharedMemorySize,
                         SMEMB);

    const int nX = BT * Dsz;    // 8M
    const int nW = Dsz * Dsz;   // 1M

    // input conversions (single fp16)
    conv_single<<<nX / 4 / 256, 256>>>(x, xf, nX / 4);
    conv_w3<<<3 * (nW / 4) / 256, 256>>>((const float*)d_in[1],
                                         (const float*)d_in[2],
                                         (const float*)d_in[3], wf, nW / 4);

    // fused QKV projection: [8192, 3072] = x @ [Wq;Wk;Wv]^T, fp16 out
    hgemm_nt<<<dim3(3 * Dsz / 128, BT / 128, 1), 256, SMEMB>>>(
        xf, wf, qkv, Dsz, Dsz, Dsz, 3 * Dsz, 0, 1, 0, 0, 0);

    const h16* qf = qkv;
    const h16* kf = qkv + Dsz;
    const h16* vf = qkv + 2 * Dsz;

    // V transpose (fp16, source stride 3072)
    transpose_h<<<dim3(Dsz / 32, Tsz / 32, Bsz), dim3(32, 8)>>>(vf, vt, 3 * Dsz);

    // S = Q @ K^T per batch (causal tile skip, heavy rows first), fp32 scores
    hgemm_nt<<<dim3(Tsz / 128, Tsz / 128, Bsz), 256, SMEMB>>>(
        qf, kf, s, Dsz, 3 * Dsz, 3 * Dsz, Tsz, 1, 0,
        (long long)Tsz * 3 * Dsz, (long long)Tsz * 3 * Dsz,
        (long long)Tsz * Tsz);

    // causal softmax -> P fp16 (tail zero-filled to 128 boundary)
    softmax_pf<<<dim3(Tsz, Bsz), 256>>>(s, pf);

    // O = P @ V (NT against V^T, K clipped to row0+128, heavy rows first)
    hgemm_nt<<<dim3(Dsz / 128, Tsz / 128, Bsz), 256, SMEMB>>>(
        pf, vt, out, Tsz, Tsz, Tsz, Dsz, 2, 0,
        (long long)Tsz * Tsz, (long long)Dsz * Tsz, (long long)Tsz * Dsz);
}

// round 6
// speedup vs baseline: 7.7368x; 1.0392x over previous
#include <cuda_runtime.h>
#include <cuda_fp16.h>
#include <stdint.h>
#include <math.h>

#define Bsz 4
#define Tsz 2048
#define Dsz 1024
#define BT  (Bsz * Tsz)

typedef __half h16;

// ---------------- scratch (__device__ globals; allocation-free rule) -------
__device__ __align__(16) float g_s[(size_t)Bsz * Tsz * Tsz];
__device__ __align__(16) h16 g_xf[(size_t)BT * Dsz];
__device__ __align__(16) h16 g_wf[3][(size_t)Dsz * Dsz];   // contiguous [3072,1024]
__device__ __align__(16) h16 g_qkv[(size_t)BT * 3 * Dsz];  // [8192, 3072] fp16
__device__ __align__(16) h16 g_pf[(size_t)Bsz * Tsz * Tsz];

// ---------------- low-level helpers (plain sm_80-era PTX only) --------------
__device__ __forceinline__ uint32_t smem_u32(const void* p) {
    uint32_t a;
    asm("{ .reg .u64 t; cvta.to.shared.u64 t, %1; cvt.u32.u64 %0, t; }"
        : "=r"(a) : "l"(p));
    return a;
}

#define CP_ASYNC16(dst, src) \
    asm volatile("cp.async.cg.shared.global [%0], [%1], 16;" \
                 :: "r"(dst), "l"(src))
#define CP_COMMIT() asm volatile("cp.async.commit_group;")
#define CP_WAIT1()  asm volatile("cp.async.wait_group 1;")

__device__ __forceinline__ void ldsm4(uint32_t& r0, uint32_t& r1,
                                      uint32_t& r2, uint32_t& r3,
                                      uint32_t addr) {
    asm volatile("ldmatrix.sync.aligned.m8n8.x4.shared.b16 {%0,%1,%2,%3}, [%4];"
                 : "=r"(r0), "=r"(r1), "=r"(r2), "=r"(r3) : "r"(addr));
}

__device__ __forceinline__ void ldsm4t(uint32_t& r0, uint32_t& r1,
                                       uint32_t& r2, uint32_t& r3,
                                       uint32_t addr) {
    asm volatile(
        "ldmatrix.sync.aligned.m8n8.x4.trans.shared.b16 {%0,%1,%2,%3}, [%4];"
        : "=r"(r0), "=r"(r1), "=r"(r2), "=r"(r3) : "r"(addr));
}

__device__ __forceinline__ void mma16816(float* d, const uint32_t* a,
                                         const uint32_t* b) {
    asm volatile(
        "mma.sync.aligned.m16n8k16.row.col.f32.f16.f16.f32 "
        "{%0,%1,%2,%3}, {%4,%5,%6,%7}, {%8,%9}, {%0,%1,%2,%3};"
        : "+f"(d[0]), "+f"(d[1]), "+f"(d[2]), "+f"(d[3])
        : "r"(a[0]), "r"(a[1]), "r"(a[2]), "r"(a[3]), "r"(b[0]), "r"(b[1]));
}

// ---------------- HMMA GEMM ---------------------------------------------------
// C[M,N] = A[M,K] * op(B).  bnn=0: B is [N,K] (NT).  bnn=1: B is [K,N] (NN).
// fp16 operands, fp32 accumulate. lda/ldb/ldc row strides (elements).
// mode 0: full.  mode 1: causal tile skip (+reversed row order).
// mode 2: kend = row0+128 (+reversed row order).
// ofp16: write C as fp16 (else fp32).
#define KC     64
#define ROWB   144               // NT tile: 128B data + 16B pad per row
#define ROWBB  272               // NN B tile: 256B data + 16B pad per k-row
#define MATB   (128 * ROWB)      // 18432 B
#define STGB   (2 * MATB)        // A tile + B tile (NN B: 64*272=17408 <= MATB)
#define NSTG   3
#define SMEMB  (NSTG * STGB)     // 110592 B

__global__ void __launch_bounds__(256, 2) hgemm(
    const h16* __restrict__ Af, const h16* __restrict__ Bf,
    void* __restrict__ Cv, int K, int lda, int ldb, int ldc,
    int mode, int ofp16, int bnn, long long sA, long long sB, long long sC)
{
    const int bz = blockIdx.z;
    Af += (size_t)bz * sA;
    Bf += (size_t)bz * sB;

    const int by = mode ? ((int)gridDim.y - 1 - (int)blockIdx.y)
                        : (int)blockIdx.y;
    const int row0 = by * 128;
    const int col0 = blockIdx.x * 128;
    if (mode == 1 && col0 >= row0 + 128) return;
    const int kend = (mode == 2) ? (row0 + 128) : K;
    const int nc = kend / KC;           // >= 2 always

    extern __shared__ char smc[];
    const uint32_t smb = smem_u32(smc);
    const int tid  = threadIdx.x;
    const int lane = tid & 31;
    const int wid  = tid >> 5;
    const int m0 = (wid & 1) * 64;      // warp tile 64x32, warps 2x4
    const int n0 = (wid >> 1) * 32;

    float acc[4][4][4];
#pragma unroll
    for (int i = 0; i < 4; i++)
#pragma unroll
        for (int j = 0; j < 4; j++)
#pragma unroll
            for (int q = 0; q < 4; q++) acc[i][j][q] = 0.f;

    const int lch  = tid & 7;      // NT: 16B chunk within 128B row
    const int lr0  = tid >> 3;     // 0..31
    const int lch2 = tid & 15;     // NN B: 16B chunk within 256B row
    const int lr2  = tid >> 4;     // 0..15

    auto do_load = [&](int st, int k0) {
        const uint32_t sb = smb + (uint32_t)st * STGB;
        const h16* pA = Af + (size_t)row0 * lda + k0;
#pragma unroll
        for (int j = 0; j < 4; j++) {
            const int row = lr0 + j * 32;
            CP_ASYNC16(sb + (uint32_t)(row * ROWB + lch * 16),
                       pA + (size_t)row * lda + lch * 8);
        }
        if (!bnn) {
            const h16* pB = Bf + (size_t)col0 * ldb + k0;
#pragma unroll
            for (int j = 0; j < 4; j++) {
                const int row = lr0 + j * 32;
                CP_ASYNC16(sb + MATB + (uint32_t)(row * ROWB + lch * 16),
                           pB + (size_t)row * ldb + lch * 8);
            }
        } else {
            const h16* pB = Bf + (size_t)k0 * ldb + col0;
#pragma unroll
            for (int j = 0; j < 4; j++) {
                const int row = lr2 + j * 16;     // k-row 0..63
                CP_ASYNC16(sb + MATB + (uint32_t)(row * ROWBB + lch2 * 16),
                           pB + (size_t)row * ldb + lch2 * 8);
            }
        }
    };

    do_load(0, 0);
    CP_COMMIT();
    do_load(1, KC);
    CP_COMMIT();

    for (int c = 0; c < nc; c++) {
        CP_WAIT1();                      // stage c resident
        __syncthreads();                 // all warps done with stage (c+2)%3
        if (c + 2 < nc) do_load((c + 2) % NSTG, (c + 2) * KC);
        CP_COMMIT();

        const uint32_t base = smb + (uint32_t)(c % NSTG) * STGB;
#pragma unroll
        for (int kk = 0; kk < 4; kk++) {          // four k16 steps per KC=64
            uint32_t a[4][4];
#pragma unroll
            for (int mi = 0; mi < 4; mi++) {
                const uint32_t ad = base +
                    (uint32_t)((m0 + mi * 16 + (lane & 15)) * ROWB +
                               (kk * 2 + (lane >> 4)) * 16);
                ldsm4(a[mi][0], a[mi][1], a[mi][2], a[mi][3], ad);
            }
            uint32_t bb[4][2];
            if (!bnn) {
#pragma unroll
                for (int np = 0; np < 2; np++) {  // [N,K]: non-trans ldsm
                    const int rb = n0 + np * 16 + (lane & 7) + ((lane >> 4) << 3);
                    const int ch = kk * 2 + ((lane >> 3) & 1);
                    const uint32_t ad = base + MATB +
                        (uint32_t)(rb * ROWB + ch * 16);
                    ldsm4(bb[np*2][0], bb[np*2][1],
                          bb[np*2+1][0], bb[np*2+1][1], ad);
                }
            } else {
#pragma unroll
                for (int g = 0; g < 2; g++) {     // [K,N]: trans ldsm
                    const uint32_t ad = base + MATB +
                        (uint32_t)((kk * 16 + (lane & 15)) * ROWBB +
                                   (n0 + g * 16 + ((lane >> 4) << 3)) * 2);
                    ldsm4t(bb[g*2][0], bb[g*2][1],
                           bb[g*2+1][0], bb[g*2+1][1], ad);
                }
            }
#pragma unroll
            for (int mi = 0; mi < 4; mi++)
#pragma unroll
                for (int ni = 0; ni < 4; ni++)
                    mma16816(acc[mi][ni], a[mi], bb[ni]);
        }
    }

    // epilogue
    const int er = lane >> 2;
    const int ec = (lane & 3) * 2;
    if (!ofp16) {
        float* C = (float*)Cv + (size_t)bz * sC;
#pragma unroll
        for (int mi = 0; mi < 4; mi++) {
            const int r = row0 + m0 + mi * 16 + er;
#pragma unroll
            for (int ni = 0; ni < 4; ni++) {
                const int cc = col0 + n0 + ni * 8 + ec;
                *(float2*)&C[(size_t)r * ldc + cc] =
                    make_float2(acc[mi][ni][0], acc[mi][ni][1]);
                *(float2*)&C[(size_t)(r + 8) * ldc + cc] =
                    make_float2(acc[mi][ni][2], acc[mi][ni][3]);
            }
        }
    } else {
        h16* C = (h16*)Cv + (size_t)bz * sC;
#pragma unroll
        for (int mi = 0; mi < 4; mi++) {
            const int r = row0 + m0 + mi * 16 + er;
#pragma unroll
            for (int ni = 0; ni < 4; ni++) {
                const int cc = col0 + n0 + ni * 8 + ec;
                __half2 h0 = __floats2half2_rn(acc[mi][ni][0], acc[mi][ni][1]);
                __half2 h1 = __floats2half2_rn(acc[mi][ni][2], acc[mi][ni][3]);
                *(__half2*)&C[(size_t)r * ldc + cc] = h0;
                *(__half2*)&C[(size_t)(r + 8) * ldc + cc] = h1;
            }
        }
    }
}

// ---------------- conversions ------------------------------------------------
__global__ void __launch_bounds__(256) conv_single(
    const float* __restrict__ in, h16* __restrict__ o, int n4)
{
    int i = blockIdx.x * 256 + threadIdx.x;
    if (i >= n4) return;
    float4 v = ((const float4*)in)[i];
    __half2 p0 = __floats2half2_rn(v.x, v.y);
    __half2 p1 = __floats2half2_rn(v.z, v.w);
    uint2 u;
    u.x = *(uint32_t*)&p0;
    u.y = *(uint32_t*)&p1;
    ((uint2*)o)[i] = u;
}

__global__ void __launch_bounds__(256) conv_w3(
    const float* __restrict__ w0, const float* __restrict__ w1,
    const float* __restrict__ w2, h16* __restrict__ o, int n4each)
{
    int i = blockIdx.x * 256 + threadIdx.x;
    if (i >= 3 * n4each) return;
    const int m = i / n4each;
    const int r = i - m * n4each;
    const float* in = (m == 0) ? w0 : (m == 1) ? w1 : w2;
    float4 v = ((const float4*)in)[r];
    __half2 p0 = __floats2half2_rn(v.x, v.y);
    __half2 p1 = __floats2half2_rn(v.z, v.w);
    uint2 u;
    u.x = *(uint32_t*)&p0;
    u.y = *(uint32_t*)&p1;
    ((uint2*)o)[i] = u;
}

// ---------------- causal softmax -> fp16 P (vectorized, fused tail-zero) ----
__device__ __forceinline__ float warp_max_f(float v) {
#pragma unroll
    for (int o = 16; o; o >>= 1) v = fmaxf(v, __shfl_xor_sync(0xffffffffu, v, o));
    return v;
}
__device__ __forceinline__ float warp_sum_f(float v) {
#pragma unroll
    for (int o = 16; o; o >>= 1) v += __shfl_xor_sync(0xffffffffu, v, o);
    return v;
}

__global__ void __launch_bounds__(256) softmax_pf(
    const float* __restrict__ S, h16* __restrict__ pf)
{
    __shared__ float es[Tsz];
    __shared__ float red[8];
    const int b = blockIdx.y;
    const int r = blockIdx.x;
    const float* row = S + ((size_t)b * Tsz + r) * Tsz;
    h16* pr = pf + ((size_t)b * Tsz + r) * Tsz;
    const int blk_end = ((r >> 7) + 1) << 7;   // padded to 128
    const int n4 = blk_end >> 2;
    const float scale = 0.03125f;              // 1/sqrt(1024)
    const int tid = threadIdx.x;

    // pass 1: masked max (vectorized)
    float m = -INFINITY;
    for (int i4 = tid; i4 < n4; i4 += 256) {
        float4 v = ((const float4*)row)[i4];
        const int base = i4 << 2;
        if (base + 3 <= r) {
            m = fmaxf(fmaxf(fmaxf(m, v.x), v.y), fmaxf(v.z, v.w));
        } else {
            if (base + 0 <= r) m = fmaxf(m, v.x);
            if (base + 1 <= r) m = fmaxf(m, v.y);
            if (base + 2 <= r) m = fmaxf(m, v.z);
            if (base + 3 <= r) m = fmaxf(m, v.w);
        }
    }
    m = warp_max_f(m);
    if ((tid & 31) == 0) red[tid >> 5] = m;
    __syncthreads();
    m = red[0];
#pragma unroll
    for (int i = 1; i < 8; i++) m = fmaxf(m, red[i]);
    __syncthreads();

    // pass 2: masked exp + sum (masked lanes contribute exact 0)
    float ssum = 0.f;
    for (int i4 = tid; i4 < n4; i4 += 256) {
        float4 v = ((const float4*)row)[i4];
        const int base = i4 << 2;
        float e0 = (base + 0 <= r) ? __expf((v.x - m) * scale) : 0.f;
        float e1 = (base + 1 <= r) ? __expf((v.y - m) * scale) : 0.f;
        float e2 = (base + 2 <= r) ? __expf((v.z - m) * scale) : 0.f;
        float e3 = (base + 3 <= r) ? __expf((v.w - m) * scale) : 0.f;
        ((float4*)es)[i4] = make_float4(e0, e1, e2, e3);
        ssum += (e0 + e1) + (e2 + e3);
    }
    ssum = warp_sum_f(ssum);
    if ((tid & 31) == 0) red[tid >> 5] = ssum;
    __syncthreads();
    ssum = 0.f;
#pragma unroll
    for (int i = 0; i < 8; i++) ssum += red[i];
    const float inv = 1.f / ssum;
    __syncthreads();

    // pass 3: normalize + write fp16 (tail zeros come for free)
    for (int i4 = tid; i4 < n4; i4 += 256) {
        float4 e = ((const float4*)es)[i4];
        __half2 h0 = __floats2half2_rn(e.x * inv, e.y * inv);
        __half2 h1 = __floats2half2_rn(e.z * inv, e.w * inv);
        uint2 u;
        u.x = *(uint32_t*)&h0;
        u.y = *(uint32_t*)&h1;
        ((uint2*)pr)[i4] = u;
    }
}

// ---------------- launch ------------------------------------------------------
extern "C" void kernel_launch(void* const* d_in, const int* in_sizes, int n_in,
                              void* d_out, int out_size)
{
    (void)in_sizes; (void)n_in; (void)out_size;
    const float* x = (const float*)d_in[0];
    float* out = (float*)d_out;

    float* s;
    h16 *xf, *wf, *qkv, *pf;
    cudaGetSymbolAddress((void**)&s,   g_s);
    cudaGetSymbolAddress((void**)&xf,  g_xf);
    cudaGetSymbolAddress((void**)&wf,  g_wf);
    cudaGetSymbolAddress((void**)&qkv, g_qkv);
    cudaGetSymbolAddress((void**)&pf,  g_pf);

    cudaFuncSetAttribute(hgemm, cudaFuncAttributeMaxDynamicSharedMemorySize,
                         SMEMB);

    const int nX = BT * Dsz;    // 8M
    const int nW = Dsz * Dsz;   // 1M

    conv_single<<<nX / 4 / 256, 256>>>(x, xf, nX / 4);
    conv_w3<<<3 * (nW / 4) / 256, 256>>>((const float*)d_in[1],
                                         (const float*)d_in[2],
                                         (const float*)d_in[3], wf, nW / 4);

    // fused QKV projection: [8192, 3072] = x @ [Wq;Wk;Wv]^T, fp16 out (NT)
    hgemm<<<dim3(3 * Dsz / 128, BT / 128, 1), 256, SMEMB>>>(
        xf, wf, qkv, Dsz, Dsz, Dsz, 3 * Dsz, 0, 1, 0, 0, 0, 0);

    const h16* qf = qkv;
    const h16* kf = qkv + Dsz;
    const h16* vf = qkv + 2 * Dsz;

    // S = Q @ K^T per batch (NT, causal tile skip, heavy rows first)
    hgemm<<<dim3(Tsz / 128, Tsz / 128, Bsz), 256, SMEMB>>>(
        qf, kf, s, Dsz, 3 * Dsz, 3 * Dsz, Tsz, 1, 0, 0,
        (long long)Tsz * 3 * Dsz, (long long)Tsz * 3 * Dsz,
        (long long)Tsz * Tsz);

    // causal softmax -> P fp16 (vectorized, tail zero-filled to 128 boundary)
    softmax_pf<<<dim3(Tsz, Bsz), 256>>>(s, pf);

    // O = P @ V (NN: V read in place from qkv, K clipped to row0+128)
    hgemm<<<dim3(Dsz / 128, Tsz / 128, Bsz), 256, SMEMB>>>(
        pf, vf, out, Tsz, Tsz, 3 * Dsz, Dsz, 2, 0, 1,
        (long long)Tsz * Tsz, (long long)Tsz * 3 * Dsz,
        (long long)Tsz * Dsz);
}